// round 1
// baseline (speedup 1.0000x reference)
#include <cuda_runtime.h>

// ---------------------------------------------------------------------------
// Problem constants (shapes are static per reference setup_inputs)
// ---------------------------------------------------------------------------
#define NE      100000          // edges
#define NORD    9               // spherical orders (L=0..2)
#define CIN     64
#define OUTC    128             // HEADS*K_C
#define HEADS   8
#define XDIM    (NORD * CIN)    // 576 floats per edge per tensor
#define NNODES  10000
#define TILE_E  16              // edges per block
#define EPAD    18              // padded edge slots per smem row (bank/align)
#define SMEM_BYTES (2 * XDIM * EPAD * 4)

typedef unsigned long long u64;

// Scratch (static device globals are the sanctioned scratch mechanism)
__device__ float    g_pre[NE * HEADS];
__device__ unsigned g_nmax[NNODES * HEADS];
__device__ float    g_nsum[NNODES * HEADS];

// ---------------------------------------------------------------------------
// SO(2) path table: out = sum over terms of sgn * x[:, i, :] @ W[w]
// Derived from _so2_paths((0,2),(0,2)); 29 terms grouped by output order o.
//   m=0: W[li*3+lo]; m=1: Wr=W[9+4a+2b], Wi=Wr+1; m=2: Wr=W[17], Wi=W[18]
// ---------------------------------------------------------------------------
__constant__ int   c_start[10] = {0, 3, 7, 10, 14, 16, 20, 23, 27, 29};
__constant__ int   c_i[29] = {0,2,6,  3,1,7,5,  0,2,6,  3,7,1,5,  8,4,
                              3,1,7,5,  0,2,6,  3,7,1,5,  8,4};
__constant__ int   c_w[29] = {0,3,6,  10,9,14,13,  1,4,7,  9,13,10,14,  18,17,
                              12,11,16,15,  2,5,8,  11,15,12,16,  17,18};
__constant__ float c_sgn[29] = {1,1,1,  1,1,1,1,  1,1,1,  1,1,-1,-1,  1,1,
                                1,1,1,1,  1,1,1,  1,1,-1,-1,  1,-1};

// ---------------------------------------------------------------------------
// Packed f32x2 helpers (FFMA 3-reg is half rate on sm_103a; f32x2 restores it)
// ---------------------------------------------------------------------------
__device__ __forceinline__ u64 pack2(float a, float b) {
    u64 r; asm("mov.b64 %0, {%1, %2};" : "=l"(r) : "f"(a), "f"(b)); return r;
}
__device__ __forceinline__ u64 fma2(u64 a, u64 b, u64 c) {
    u64 d; asm("fma.rn.f32x2 %0, %1, %2, %3;" : "=l"(d) : "l"(a), "l"(b), "l"(c));
    return d;
}
__device__ __forceinline__ void unpack2(u64 v, float& a, float& b) {
    asm("mov.b64 {%0, %1}, %2;" : "=f"(a), "=f"(b) : "l"(v));
}

// ---------------------------------------------------------------------------
// Kernel 1: fused SO(2) linear (q & k) + per-head dot -> g_pre[e,h]
// Block: 128 threads = 128 output channels; 16 edges staged in smem
// (transposed, edge-pairs contiguous so LDS.64 feeds packed FMA2).
// ---------------------------------------------------------------------------
__global__ void __launch_bounds__(128)
pre_kernel(const float* __restrict__ xq, const float* __restrict__ xk,
           const float* __restrict__ Wq, const float* __restrict__ Wk)
{
    extern __shared__ float sm[];
    float* sqf = sm;                    // [XDIM][EPAD]
    float* skf = sm + XDIM * EPAD;

    const int tid = threadIdx.x;
    const int e0  = blockIdx.x * TILE_E;

    // Stage x tiles transposed: coalesced global reads, strided smem writes
    for (int idx = tid; idx < TILE_E * XDIM; idx += 128) {
        int e  = idx / XDIM;
        int dd = idx - e * XDIM;
        sqf[dd * EPAD + e] = xq[(e0 + e) * XDIM + dd];
        skf[dd * EPAD + e] = xk[(e0 + e) * XDIM + dd];
    }
    __syncthreads();

    const u64* sq2 = (const u64*)sqf;   // row stride = EPAD/2 = 9 u64
    const u64* sk2 = (const u64*)skf;

    const int c = tid;                  // output channel 0..127
    const float* wqc = Wq + c;
    const float* wkc = Wk + c;

    u64 pre2[TILE_E / 2];
    #pragma unroll
    for (int j = 0; j < TILE_E / 2; ++j) pre2[j] = 0ull;

    for (int o = 0; o < NORD; ++o) {
        u64 qa[TILE_E / 2], ka[TILE_E / 2];
        #pragma unroll
        for (int j = 0; j < TILE_E / 2; ++j) { qa[j] = 0ull; ka[j] = 0ull; }

        const int t_beg = c_start[o], t_end = c_start[o + 1];
        for (int t = t_beg; t < t_end; ++t) {
            const int   i   = c_i[t];
            const int   w   = c_w[t];
            const float sgn = c_sgn[t];
            const float* wq = wqc + w * (CIN * OUTC);
            const float* wk = wkc + w * (CIN * OUTC);
            const u64*  xr  = sq2 + i * CIN * (EPAD / 2);
            const u64*  yr  = sk2 + i * CIN * (EPAD / 2);

            #pragma unroll 4
            for (int d = 0; d < CIN; ++d) {
                float wqv = sgn * __ldg(wq + d * OUTC);   // L2-hot, 512B/warp
                float wkv = sgn * __ldg(wk + d * OUTC);
                u64 w2q = pack2(wqv, wqv);
                u64 w2k = pack2(wkv, wkv);
                const u64* xrow = xr + d * (EPAD / 2);
                const u64* yrow = yr + d * (EPAD / 2);
                #pragma unroll
                for (int j = 0; j < TILE_E / 2; ++j) {
                    qa[j] = fma2(xrow[j], w2q, qa[j]);    // smem broadcast
                    ka[j] = fma2(yrow[j], w2k, ka[j]);
                }
            }
        }
        #pragma unroll
        for (int j = 0; j < TILE_E / 2; ++j)
            pre2[j] = fma2(qa[j], ka[j], pre2[j]);        // dot accumulation
    }

    // Reduce over the 16 channels of each head (lanes c..c+15 share a head)
    const float scale = 0.25f;                            // K_C^{-1/2}
    #pragma unroll
    for (int j = 0; j < TILE_E / 2; ++j) {
        float p0, p1;
        unpack2(pre2[j], p0, p1);
        #pragma unroll
        for (int off = 8; off; off >>= 1) {
            p0 += __shfl_xor_sync(0xffffffffu, p0, off);
            p1 += __shfl_xor_sync(0xffffffffu, p1, off);
        }
        if ((c & 15) == 0) {
            int h = c >> 4;
            g_pre[(e0 + 2 * j)     * HEADS + h] = p0 * scale;
            g_pre[(e0 + 2 * j + 1) * HEADS + h] = p1 * scale;
        }
    }
}

// ---------------------------------------------------------------------------
// Segment softmax: monotonic uint encoding for float atomicMax
// ---------------------------------------------------------------------------
__device__ __forceinline__ unsigned enc_f(float f) {
    unsigned u = __float_as_uint(f);
    return (u & 0x80000000u) ? ~u : (u | 0x80000000u);
}
__device__ __forceinline__ float dec_f(unsigned u) {
    return (u & 0x80000000u) ? __uint_as_float(u ^ 0x80000000u)
                             : __uint_as_float(~u);
}

__global__ void init_kernel() {
    int i = blockIdx.x * blockDim.x + threadIdx.x;
    if (i < NNODES * HEADS) { g_nmax[i] = 0u; g_nsum[i] = 0.0f; }
}

__global__ void max_kernel(const int* __restrict__ index) {
    int i = blockIdx.x * blockDim.x + threadIdx.x;
    if (i >= NE * HEADS) return;
    int e = i >> 3, h = i & 7;
    atomicMax(&g_nmax[index[e] * HEADS + h], enc_f(g_pre[i]));
}

__global__ void ex_kernel(const int* __restrict__ index, float* __restrict__ out) {
    int i = blockIdx.x * blockDim.x + threadIdx.x;
    if (i >= NE * HEADS) return;
    int e = i >> 3, h = i & 7;
    int n = index[e] * HEADS + h;
    float ex = expf(g_pre[i] - dec_f(g_nmax[n]));
    out[i] = ex;
    atomicAdd(&g_nsum[n], ex);
}

__global__ void div_kernel(const int* __restrict__ index, float* __restrict__ out) {
    int i = blockIdx.x * blockDim.x + threadIdx.x;
    if (i >= NE * HEADS) return;
    int e = i >> 3, h = i & 7;
    out[i] = out[i] / (g_nsum[index[e] * HEADS + h] + 1e-16f);
}

// ---------------------------------------------------------------------------
extern "C" void kernel_launch(void* const* d_in, const int* in_sizes, int n_in,
                              void* d_out, int out_size)
{
    const float* xq    = (const float*)d_in[0];
    const float* xk    = (const float*)d_in[1];
    const float* Wq    = (const float*)d_in[2];
    const float* Wk    = (const float*)d_in[3];
    const int*   index = (const int*)d_in[4];
    float*       out   = (float*)d_out;

    cudaFuncSetAttribute(pre_kernel,
                         cudaFuncAttributeMaxDynamicSharedMemorySize, SMEM_BYTES);

    pre_kernel<<<NE / TILE_E, 128, SMEM_BYTES>>>(xq, xk, Wq, Wk);

    const int T = 256;
    init_kernel<<<(NNODES * HEADS + T - 1) / T, T>>>();
    max_kernel <<<(NE * HEADS + T - 1) / T, T>>>(index);
    ex_kernel  <<<(NE * HEADS + T - 1) / T, T>>>(index, out);
    div_kernel <<<(NE * HEADS + T - 1) / T, T>>>(index, out);
}

// round 3
// speedup vs baseline: 6.8264x; 6.8264x over previous
#include <cuda_runtime.h>
#include <cuda_bf16.h>

// ---------------------------------------------------------------------------
// Static problem shape
// ---------------------------------------------------------------------------
#define NE      100000
#define NNODES  10000
#define HEADS   8
#define XDIM    576
#define MT      128                       // edges per CTA
#define NGRID   ((NE + MT - 1) / MT)      // 782
#define THREADS 256

#define ASTRIDE 144                       // padded row stride (bytes): 64 bf16 + 16B pad
#define TILE_B  (128 * ASTRIDE)           // 18432 per split tile
#define OFF_AHI 0u
#define OFF_ALO 18432u
#define OFF_BHI 36864u
#define OFF_BLO 55296u
#define BUF     73728u
#define SMEM_TOTAL (2 * BUF)              // 147456

typedef unsigned int u32;

// ---------------------------------------------------------------------------
// SO(2) path tables (validated round 1: rel_err 1e-6 with this mapping)
// ---------------------------------------------------------------------------
__constant__ int   c_i[29] = {0,2,6,  3,1,7,5,  0,2,6,  3,7,1,5,  8,4,
                              3,1,7,5,  0,2,6,  3,7,1,5,  8,4};
__constant__ int   c_w[29] = {0,3,6,  10,9,14,13,  1,4,7,  9,13,10,14,  18,17,
                              12,11,16,15,  2,5,8,  11,15,12,16,  17,18};
__constant__ float c_sgn[29] = {1,1,1,  1,1,1,1,  1,1,1,  1,1,-1,-1,  1,1,
                                1,1,1,1,  1,1,1,  1,1,-1,-1,  1,-1};

// Flattened (order, side, term) schedule: 58 steps.
__constant__ unsigned char stt[58] = {
    0,1,2, 0,1,2,
    3,4,5,6, 3,4,5,6,
    7,8,9, 7,8,9,
    10,11,12,13, 10,11,12,13,
    14,15, 14,15,
    16,17,18,19, 16,17,18,19,
    20,21,22, 20,21,22,
    23,24,25,26, 23,24,25,26,
    27,28, 27,28};
__constant__ unsigned char sside[58] = {
    0,0,0, 1,1,1,
    0,0,0,0, 1,1,1,1,
    0,0,0, 1,1,1,
    0,0,0,0, 1,1,1,1,
    0,0, 1,1,
    0,0,0,0, 1,1,1,1,
    0,0,0, 1,1,1,
    0,0,0,0, 1,1,1,1,
    0,0, 1,1};
// bit0 = zero this side's accumulator before the term; bit1 = dot after step
__constant__ unsigned char sflag[58] = {
    1,0,0, 1,0,2,
    1,0,0,0, 1,0,0,2,
    1,0,0, 1,0,2,
    1,0,0,0, 1,0,0,2,
    1,0, 1,2,
    1,0,0,0, 1,0,0,2,
    1,0,0, 1,0,2,
    1,0,0,0, 1,0,0,2,
    1,0, 1,2};

// ---------------------------------------------------------------------------
// Scratch
// ---------------------------------------------------------------------------
__device__ float    g_pre[NE * HEADS];
__device__ unsigned g_nmax[NNODES * HEADS];
__device__ float    g_nsum[NNODES * HEADS];
// prepped B^T: [29 terms][2 splits][128 n][64 k] bf16, sign folded
__device__ __align__(16) __nv_bfloat16 g_prepQ[29 * 2 * 8192];
__device__ __align__(16) __nv_bfloat16 g_prepK[29 * 2 * 8192];

// ---------------------------------------------------------------------------
// PTX helpers (baseline sm_80+ features only — no tcgen05 on this toolchain)
// ---------------------------------------------------------------------------
__device__ __forceinline__ u32 smem_u32(const void* p) {
    u32 a;
    asm("{ .reg .u64 t; cvta.to.shared.u64 t, %1; cvt.u32.u64 %0, t; }"
        : "=r"(a) : "l"(p));
    return a;
}
__device__ __forceinline__ void ldsm4(u32 addr, u32* r) {
    asm volatile("ldmatrix.sync.aligned.m8n8.x4.shared.b16 {%0,%1,%2,%3}, [%4];"
                 : "=r"(r[0]), "=r"(r[1]), "=r"(r[2]), "=r"(r[3]) : "r"(addr));
}
__device__ __forceinline__ void mma16816(float* d, const u32* a, u32 b0, u32 b1) {
    asm volatile(
        "mma.sync.aligned.m16n8k16.row.col.f32.bf16.bf16.f32 "
        "{%0,%1,%2,%3}, {%4,%5,%6,%7}, {%8,%9}, {%0,%1,%2,%3};"
        : "+f"(d[0]), "+f"(d[1]), "+f"(d[2]), "+f"(d[3])
        : "r"(a[0]), "r"(a[1]), "r"(a[2]), "r"(a[3]), "r"(b0), "r"(b1));
}
__device__ __forceinline__ void cp16(u32 dst, const void* src) {
    asm volatile("cp.async.cg.shared.global [%0], [%1], 16;"
                 :: "r"(dst), "l"(__cvta_generic_to_global(src)) : "memory");
}
// split two floats into packed bf16 hi pair + lo pair
__device__ __forceinline__ void split2(float x, float y, u32& hi, u32& lo) {
    __nv_bfloat162 h2 = __floats2bfloat162_rn(x, y);    // x -> low half
    u32 hu; { hu = *reinterpret_cast<u32*>(&h2); }
    float xh = __uint_as_float(hu << 16);
    float yh = __uint_as_float(hu & 0xffff0000u);
    __nv_bfloat162 l2 = __floats2bfloat162_rn(x - xh, y - yh);
    hi = hu;
    lo = *reinterpret_cast<u32*>(&l2);
}

// ---------------------------------------------------------------------------
// Prep: split W into bf16 hi/lo, transpose to B^T[n][k], fold sign.
// ---------------------------------------------------------------------------
__global__ void prep_kernel(const float* __restrict__ Wq,
                            const float* __restrict__ Wk)
{
    int idx = blockIdx.x * blockDim.x + threadIdx.x;
    if (idx >= 29 * 8192) return;
    int t = idx >> 13;
    int r = idx & 8191;
    int d = r >> 7;          // k 0..63
    int c = r & 127;         // n 0..127
    float s = c_sgn[t];
    size_t src = (size_t)c_w[t] * 8192 + (size_t)d * 128 + c;
    size_t dhi = (size_t)t * 16384 + (size_t)c * 64 + d;

    float vq = s * Wq[src];
    __nv_bfloat16 qh = __float2bfloat16(vq);
    g_prepQ[dhi]        = qh;
    g_prepQ[dhi + 8192] = __float2bfloat16(vq - __bfloat162float(qh));

    float vk = s * Wk[src];
    __nv_bfloat16 kh = __float2bfloat16(vk);
    g_prepK[dhi]        = kh;
    g_prepK[dhi + 8192] = __float2bfloat16(vk - __bfloat162float(kh));
}

// ---------------------------------------------------------------------------
// Per-term MMA: bf16x3 split, warp tile 32(M) x 64(N).
// ---------------------------------------------------------------------------
__device__ __forceinline__ void term_mma(float (&acc)[2][8][4],
                                         u32 aHi, u32 aLo, u32 bHi, u32 bLo,
                                         int lane)
{
    const u32 aRow = (u32)(lane & 15) * ASTRIDE + (u32)(lane >> 4) * 16u;
    const u32 bRow = (u32)((lane & 7) | ((lane & 16) >> 1)) * ASTRIDE
                   + (u32)((lane >> 3) & 1) * 16u;
    #pragma unroll
    for (int ks = 0; ks < 4; ++ks) {
        const u32 kb = (u32)ks * 32u;
        u32 ah0[4], ah1[4], al0[4], al1[4];
        ldsm4(aHi + aRow + kb, ah0);
        ldsm4(aHi + aRow + 16u * ASTRIDE + kb, ah1);
        ldsm4(aLo + aRow + kb, al0);
        ldsm4(aLo + aRow + 16u * ASTRIDE + kb, al1);
        #pragma unroll
        for (int np = 0; np < 4; ++np) {
            const u32 bo = bRow + (u32)np * (16u * ASTRIDE) + kb;
            u32 bh[4], bl[4];
            ldsm4(bHi + bo, bh);
            mma16816(acc[0][np*2],   ah0, bh[0], bh[1]);
            mma16816(acc[0][np*2+1], ah0, bh[2], bh[3]);
            mma16816(acc[1][np*2],   ah1, bh[0], bh[1]);
            mma16816(acc[1][np*2+1], ah1, bh[2], bh[3]);
            mma16816(acc[0][np*2],   al0, bh[0], bh[1]);
            mma16816(acc[0][np*2+1], al0, bh[2], bh[3]);
            mma16816(acc[1][np*2],   al1, bh[0], bh[1]);
            mma16816(acc[1][np*2+1], al1, bh[2], bh[3]);
            ldsm4(bLo + bo, bl);
            mma16816(acc[0][np*2],   ah0, bl[0], bl[1]);
            mma16816(acc[0][np*2+1], ah0, bl[2], bl[3]);
            mma16816(acc[1][np*2],   ah1, bl[0], bl[1]);
            mma16816(acc[1][np*2+1], ah1, bl[2], bl[3]);
        }
    }
}

// ---------------------------------------------------------------------------
// Main kernel
// ---------------------------------------------------------------------------
__global__ void __launch_bounds__(THREADS, 1)
pre_kernel(const float* __restrict__ xq, const float* __restrict__ xk)
{
    extern __shared__ char smem[];
    const u32 sb   = smem_u32(smem);
    const int tid  = threadIdx.x;
    const int lane = tid & 31;
    const int wid  = tid >> 5;
    const int e0   = blockIdx.x * MT;
    const int m0   = (wid >> 1) * 32;     // warp row base
    const int n0   = (wid & 1) * 64;      // warp col base

    // ---- staging helpers --------------------------------------------------
    auto issueA = [&](int s, float4* av) {
        const float* __restrict__ x = sside[s] ? xk : xq;
        const float* base = x + (size_t)e0 * XDIM + c_i[stt[s]] * 64;
        #pragma unroll
        for (int it = 0; it < 8; ++it) {
            int idx = tid + it * THREADS;
            int row = idx >> 4;
            int c4  = idx & 15;
            if (e0 + row < NE)
                av[it] = *(const float4*)(base + (size_t)row * XDIM + (c4 << 2));
            else
                av[it] = make_float4(0.f, 0.f, 0.f, 0.f);
        }
    };
    auto issueB = [&](int s) {
        const __nv_bfloat16* wp = sside[s] ? g_prepK : g_prepQ;
        const __nv_bfloat16* bb = wp + (size_t)stt[s] * 16384;
        const u32 dstb = sb + (u32)((s & 1)) * BUF + OFF_BHI;
        #pragma unroll
        for (int it = 0; it < 8; ++it) {
            int idx = tid + it * THREADS;          // 0..2047
            int split = idx >> 10;
            int rem   = idx & 1023;
            int r     = rem >> 3;
            int c16   = rem & 7;
            cp16(dstb + (u32)split * TILE_B + (u32)r * ASTRIDE + (u32)c16 * 16u,
                 bb + (size_t)split * 8192 + (size_t)r * 64 + (c16 << 3));
        }
        asm volatile("cp.async.commit_group;" ::: "memory");
    };
    auto storeA = [&](int s, const float4* av) {
        char* dstHi = smem + (s & 1) * BUF + OFF_AHI;
        char* dstLo = smem + (s & 1) * BUF + OFF_ALO;
        #pragma unroll
        for (int it = 0; it < 8; ++it) {
            int idx = tid + it * THREADS;
            int row = idx >> 4;
            int c4  = idx & 15;
            u32 h01, l01, h23, l23;
            split2(av[it].x, av[it].y, h01, l01);
            split2(av[it].z, av[it].w, h23, l23);
            u32 off = (u32)row * ASTRIDE + (u32)c4 * 8u;
            *(uint2*)(dstHi + off) = make_uint2(h01, h23);
            *(uint2*)(dstLo + off) = make_uint2(l01, l23);
        }
    };

    // ---- accumulators ------------------------------------------------------
    float qacc[2][8][4], kacc[2][8][4], preacc[4][2][2];
    #pragma unroll
    for (int a = 0; a < 4; ++a)
        #pragma unroll
        for (int b = 0; b < 2; ++b) { preacc[a][b][0] = 0.f; preacc[a][b][1] = 0.f; }

    // ---- prologue: stage step 0 --------------------------------------------
    {
        float4 av0[8];
        issueA(0, av0);
        issueB(0);
        storeA(0, av0);
        asm volatile("cp.async.wait_group 0;" ::: "memory");
        __syncthreads();
    }

    // ---- main loop ----------------------------------------------------------
    for (int s = 0; s < 58; ++s) {
        float4 av[8];
        const bool more = (s + 1 < 58);
        if (more) { issueA(s + 1, av); issueB(s + 1); }

        const u32 bufb = sb + (u32)(s & 1) * BUF
                       + (u32)m0 * ASTRIDE;          // A row base folded in
        const u32 bufn = sb + (u32)(s & 1) * BUF + (u32)n0 * ASTRIDE;
        const int  sd  = sside[s];
        const int  fl  = sflag[s];

        if (sd == 0) {
            if (fl & 1) {
                #pragma unroll
                for (int i = 0; i < 2; ++i)
                    #pragma unroll
                    for (int j = 0; j < 8; ++j)
                        #pragma unroll
                        for (int r = 0; r < 4; ++r) qacc[i][j][r] = 0.f;
            }
            term_mma(qacc, bufb + OFF_AHI, bufb + OFF_ALO,
                     bufn + OFF_BHI, bufn + OFF_BLO, lane);
        } else {
            if (fl & 1) {
                #pragma unroll
                for (int i = 0; i < 2; ++i)
                    #pragma unroll
                    for (int j = 0; j < 8; ++j)
                        #pragma unroll
                        for (int r = 0; r < 4; ++r) kacc[i][j][r] = 0.f;
            }
            term_mma(kacc, bufb + OFF_AHI, bufb + OFF_ALO,
                     bufn + OFF_BHI, bufn + OFF_BLO, lane);
        }

        if (more) storeA(s + 1, av);
        asm volatile("cp.async.wait_group 0;" ::: "memory");
        __syncthreads();

        if (fl & 2) {   // order finished: per-head dot, register-only
            #pragma unroll
            for (int mt = 0; mt < 2; ++mt)
                #pragma unroll
                for (int hl = 0; hl < 4; ++hl) {
                    int nt0 = hl * 2, nt1 = nt0 + 1;
                    preacc[hl][mt][0] +=
                        qacc[mt][nt0][0] * kacc[mt][nt0][0] +
                        qacc[mt][nt0][1] * kacc[mt][nt0][1] +
                        qacc[mt][nt1][0] * kacc[mt][nt1][0] +
                        qacc[mt][nt1][1] * kacc[mt][nt1][1];
                    preacc[hl][mt][1] +=
                        qacc[mt][nt0][2] * kacc[mt][nt0][2] +
                        qacc[mt][nt0][3] * kacc[mt][nt0][3] +
                        qacc[mt][nt1][2] * kacc[mt][nt1][2] +
                        qacc[mt][nt1][3] * kacc[mt][nt1][3];
                }
        }
    }

    // ---- reduce across the 4 lanes sharing a row, store ---------------------
    #pragma unroll
    for (int hl = 0; hl < 4; ++hl)
        #pragma unroll
        for (int mt = 0; mt < 2; ++mt)
            #pragma unroll
            for (int half = 0; half < 2; ++half) {
                float v = preacc[hl][mt][half];
                v += __shfl_xor_sync(0xffffffffu, v, 1);
                v += __shfl_xor_sync(0xffffffffu, v, 2);
                int row = e0 + m0 + mt * 16 + half * 8 + (lane >> 2);
                if ((lane & 3) == 0 && row < NE)
                    g_pre[row * HEADS + (n0 >> 4) + hl] = v * 0.25f;
            }
}

// ---------------------------------------------------------------------------
// Segment softmax (unchanged, passing in round 1)
// ---------------------------------------------------------------------------
__device__ __forceinline__ unsigned enc_f(float f) {
    unsigned u = __float_as_uint(f);
    return (u & 0x80000000u) ? ~u : (u | 0x80000000u);
}
__device__ __forceinline__ float dec_f(unsigned u) {
    return (u & 0x80000000u) ? __uint_as_float(u ^ 0x80000000u)
                             : __uint_as_float(~u);
}
__global__ void init_kernel() {
    int i = blockIdx.x * blockDim.x + threadIdx.x;
    if (i < NNODES * HEADS) { g_nmax[i] = 0u; g_nsum[i] = 0.0f; }
}
__global__ void max_kernel(const int* __restrict__ index) {
    int i = blockIdx.x * blockDim.x + threadIdx.x;
    if (i >= NE * HEADS) return;
    int e = i >> 3, h = i & 7;
    atomicMax(&g_nmax[index[e] * HEADS + h], enc_f(g_pre[i]));
}
__global__ void ex_kernel(const int* __restrict__ index, float* __restrict__ out) {
    int i = blockIdx.x * blockDim.x + threadIdx.x;
    if (i >= NE * HEADS) return;
    int e = i >> 3, h = i & 7;
    int n = index[e] * HEADS + h;
    float ex = expf(g_pre[i] - dec_f(g_nmax[n]));
    out[i] = ex;
    atomicAdd(&g_nsum[n], ex);
}
__global__ void div_kernel(const int* __restrict__ index, float* __restrict__ out) {
    int i = blockIdx.x * blockDim.x + threadIdx.x;
    if (i >= NE * HEADS) return;
    int e = i >> 3, h = i & 7;
    out[i] = out[i] / (g_nsum[index[e] * HEADS + h] + 1e-16f);
}

// ---------------------------------------------------------------------------
extern "C" void kernel_launch(void* const* d_in, const int* in_sizes, int n_in,
                              void* d_out, int out_size)
{
    const float* xq    = (const float*)d_in[0];
    const float* xk    = (const float*)d_in[1];
    const float* Wq    = (const float*)d_in[2];
    const float* Wk    = (const float*)d_in[3];
    const int*   index = (const int*)d_in[4];
    float*       out   = (float*)d_out;

    cudaFuncSetAttribute(pre_kernel,
                         cudaFuncAttributeMaxDynamicSharedMemorySize, SMEM_TOTAL);

    prep_kernel<<<(29 * 8192 + 255) / 256, 256>>>(Wq, Wk);
    pre_kernel<<<NGRID, THREADS, SMEM_TOTAL>>>(xq, xk);

    const int T = 256;
    init_kernel<<<(NNODES * HEADS + T - 1) / T, T>>>();
    max_kernel <<<(NE * HEADS + T - 1) / T, T>>>(index);
    ex_kernel  <<<(NE * HEADS + T - 1) / T, T>>>(index, out);
    div_kernel <<<(NE * HEADS + T - 1) / T, T>>>(index, out);
}